// round 7
// baseline (speedup 1.0000x reference)
#include <cuda_runtime.h>
#include <cuda_bf16.h>
#include <cstdint>

#define T_LEN     131072
#define N_ST      256
#define CR_ROWS   48         // cost ring rows (6 chunks x 8)
#define CR_BYTES  (CR_ROWS * 1024)
#define UR_SLOTS  64         // u ring slots (128 floats each)
#define UR_BYTES  (UR_SLOTS * 512)
#define SMEM_BYTES (CR_BYTES + UR_BYTES + 128)
#define FLT_MIN_N 1.17549435e-38f

// Scratch: per-step branch costs, cost[t][s] = -log(probs[t][s]). 128 MB.
static __device__ float g_cost[T_LEN * N_ST];

// ---------------------------------------------------------------------------
// Phase A: parallel likelihoods (validated rounds 1-6; FTZ emulation is the
// load-bearing fix). One warp per sample t; strided states s = lane + 32k;
// shfl.down 16..1 tree; lane-0 S broadcast; libdevice expf/logf; flush
// subnormal p and q to zero (XLA-GPU FTZ semantics -> +inf costs).
// ---------------------------------------------------------------------------
__global__ void __launch_bounds__(256) va_cost_kernel(const float* __restrict__ rx,
                                                      const float* __restrict__ h,
                                                      float* __restrict__ out) {
    __shared__ float sp[N_ST];
    __shared__ float hs[8];
    const int tid = threadIdx.x;
    if (tid < 8) hs[tid] = h[tid];
    __syncthreads();
    {
        float acc = 0.0f;
#pragma unroll
        for (int j = 0; j < 8; ++j) {
            float sym = ((tid >> (7 - j)) & 1) ? -1.0f : 1.0f;
            acc += sym * hs[j];
        }
        sp[tid] = acc;
    }
    __syncthreads();

    const int lane = tid & 31;
    const int t    = blockIdx.x * 8 + (tid >> 5);
    const float r  = rx[t];

    float p[8];
    float acc = 0.0f;
#pragma unroll
    for (int k = 0; k < 8; ++k) {
        float d = r - sp[lane + 32 * k];
        float a = (-(d * d)) / 0.2f;
        float e = expf(a);
        p[k] = (e < FLT_MIN_N) ? 0.0f : e;   // FTZ
        acc += p[k];
    }
#pragma unroll
    for (int off = 16; off > 0; off >>= 1)
        acc += __shfl_down_sync(0xffffffffu, acc, off);
    const float S = __shfl_sync(0xffffffffu, acc, 0);

    float bv = -1.0f; int bi = 0;
#pragma unroll
    for (int k = 0; k < 8; ++k) {
        float q = __fdiv_rn(p[k], S);
        q = (q < FLT_MIN_N) ? 0.0f : q;      // FTZ
        int s = lane + 32 * k;
        if (q > bv) { bv = q; bi = s; }
        g_cost[t * N_ST + s] = -logf(q);
    }
#pragma unroll
    for (int off = 16; off > 0; off >>= 1) {
        float ov = __shfl_xor_sync(0xffffffffu, bv, off);
        int   oi = __shfl_xor_sync(0xffffffffu, bi, off);
        if (ov > bv || (ov == bv && oi < bi)) { bv = ov; bi = oi; }
    }

    if (lane == 0) {
        out[T_LEN + t]     = (float)(bi & 1);
        out[2 * T_LEN + t] = bv;
    }
}

// --- cta-scope release/acquire on shared counters -------------------------
__device__ __forceinline__ void st_rel(int* p, int v) {
    asm volatile("st.release.cta.shared.b32 [%0], %1;"
                 :: "r"((unsigned)__cvta_generic_to_shared(p)), "r"(v) : "memory");
}
__device__ __forceinline__ int ld_acq(int* p) {
    int v;
    asm volatile("ld.acquire.cta.shared.b32 %0, [%1];"
                 : "=r"(v) : "r"((unsigned)__cvta_generic_to_shared(p)) : "memory");
    return v;
}

// ---------------------------------------------------------------------------
// Phase B: warp-specialized serial trellis.
//   warp 0 (producer): u recursion only. Per step: 2 LDS.128 (costs from a
//     48-row cp.async ring), 8 SHFL, 8 FADD, 4 FMNMX, 1 STS.128 exporting u
//     to a 64-slot ring. Publishes prod_steps every 16 steps (release).
//   warp 1 (consumer): bit_t = argmin(u_t) % 2 (first-index ties) + STG.
//     Pure consumer of u_t — off the critical chain, on its own SMSP.
// Producer runs T steps (exports u_1..u_T; u_T unused). bit_0 = 0 constant.
// ---------------------------------------------------------------------------
__global__ void __launch_bounds__(64) va_viterbi_kernel(float* __restrict__ out) {
    extern __shared__ char smem[];
    char*  cring = smem;                               // 48 KB cost ring
    float* uring = (float*)(smem + CR_BYTES);          // 32 KB u ring
    int*   ctrs  = (int*)(smem + CR_BYTES + UR_BYTES); // [0]=prod, [16]=cons

    const int tid  = threadIdx.x;
    const int lane = tid & 31;
    const int warp = tid >> 5;

    if (tid == 0) { ctrs[0] = 0; ctrs[16] = 0; }
    __syncthreads();

    if (warp == 0) {
        // ---------------- producer ----------------
        const unsigned cbase = (unsigned)__cvta_generic_to_shared(cring);
        // prefill 5 chunks (rows 0..39)
        for (int c = 0; c < 5; ++c) {
#pragma unroll
            for (int r = 0; r < 8; ++r) {
                int row = c * 8 + r;
                unsigned dst = cbase + (unsigned)(row * 1024 + lane * 32);
                const float* src = &g_cost[(size_t)row * N_ST + lane * 8];
                asm volatile("cp.async.cg.shared.global [%0], [%1], 16;\n"
                             "cp.async.cg.shared.global [%2], [%3], 16;\n"
                             :: "r"(dst), "l"(src), "r"(dst + 16u), "l"(src + 4) : "memory");
            }
            asm volatile("cp.async.commit_group;" ::: "memory");
        }

        float u0 = 0.0f, u1 = 0.0f, u2 = 0.0f, u3 = 0.0f;
        const int src0 = (2 * lane) & 31;
        const int src1 = (2 * lane + 1) & 31;
        unsigned co = (unsigned)(lane * 32);     // cost slot byte offset (+lane)
        unsigned uo = (unsigned)(512 + lane * 16); // u slot 1 (+lane)

        const int NCH = T_LEN / 8;               // 16384 chunks of 8 steps
        for (int c = 0; c < NCH; ++c) {
            if ((c & 1) == 0) {
                // backpressure: u slot for step s+16 collides with u_{s-48}
                int s = c * 8;
                while (ld_acq(&ctrs[16]) < s - 48) { }
            }
            asm volatile("cp.async.wait_group 4;" ::: "memory");
#pragma unroll
            for (int k = 0; k < 8; ++k) {
                const int t = c * 8 + k;
                float4 ca = *(const float4*)(cring + co);
                float4 cb = *(const float4*)(cring + co + 16);

                float a0 = __shfl_sync(0xffffffffu, u0, src0);
                float a1 = __shfl_sync(0xffffffffu, u1, src0);
                float a2 = __shfl_sync(0xffffffffu, u2, src0);
                float a3 = __shfl_sync(0xffffffffu, u3, src0);
                float b0 = __shfl_sync(0xffffffffu, u0, src1);
                float b1 = __shfl_sync(0xffffffffu, u1, src1);
                float b2 = __shfl_sync(0xffffffffu, u2, src1);
                float b3 = __shfl_sync(0xffffffffu, u3, src1);
                u0 = fminf(a0 + ca.x, a1 + ca.y);
                u1 = fminf(a2 + ca.z, a3 + ca.w);
                u2 = fminf(b0 + cb.x, b1 + cb.y);
                u3 = fminf(b2 + cb.z, b3 + cb.w);

                // export u_{t+1}
                *(float4*)((char*)uring + uo) = make_float4(u0, u1, u2, u3);
                uo += 512; if (uo >= (unsigned)UR_BYTES) uo -= (unsigned)UR_BYTES;

                // refill row t+40 into its ring slot
                int tp = t + 40;
                unsigned ro = co + 40u * 1024u;
                if (ro >= (unsigned)CR_BYTES) ro -= (unsigned)CR_BYTES;
                if (tp < T_LEN) {
                    unsigned dst = cbase + ro;
                    const float* srcp = &g_cost[(size_t)tp * N_ST + lane * 8];
                    asm volatile("cp.async.cg.shared.global [%0], [%1], 16;\n"
                                 "cp.async.cg.shared.global [%2], [%3], 16;\n"
                                 :: "r"(dst), "l"(srcp), "r"(dst + 16u), "l"(srcp + 4) : "memory");
                }
                co += 1024; if (co >= (unsigned)CR_BYTES) co -= (unsigned)CR_BYTES;
            }
            asm volatile("cp.async.commit_group;" ::: "memory");
            if (c & 1) {
                __syncwarp();
                if (lane == 0) st_rel(&ctrs[0], (c + 1) * 8);  // u_1..u_{8(c+1)} ready
            }
        }
        __syncwarp();
        if (lane == 0) st_rel(&ctrs[0], T_LEN);
    } else {
        // ---------------- consumer ----------------
        if (lane == 0) out[0] = 0.0f;   // bit_0 = argmin(zeros)%2 = 0
        const int base_li = 4 * lane;
        for (int t0 = 1; t0 < T_LEN; t0 += 16) {
            int te = t0 + 15; if (te > T_LEN - 1) te = T_LEN - 1;
            while (ld_acq(&ctrs[0]) < te) { }
#pragma unroll 4
            for (int t = t0; t <= te; ++t) {
                const float4 uu = *((const float4*)(uring + (t & 63) * 128) + lane);
                float lv = uu.x; int li = base_li;
                if (uu.y < lv) { lv = uu.y; li = base_li + 1; }
                if (uu.z < lv) { lv = uu.z; li = base_li + 2; }
                if (uu.w < lv) { lv = uu.w; li = base_li + 3; }
                unsigned lb = __float_as_uint(lv);   // u >= +0 -> uint order ok
                unsigned mv, idx;
                asm volatile("redux.sync.min.u32 %0, %1, 0xffffffff;" : "=r"(mv) : "r"(lb));
                unsigned cand = (lb == mv) ? (unsigned)li : 0xffffffffu;
                asm volatile("redux.sync.min.u32 %0, %1, 0xffffffff;" : "=r"(idx) : "r"(cand));
                if (lane == 0) out[t] = (idx & 1u) ? 1.0f : 0.0f;
            }
            __syncwarp();
            if (lane == 0) st_rel(&ctrs[16], te);
        }
    }
}

// ---------------------------------------------------------------------------
// out layout = [detected(T) | confident_bits(T) | confidence(T)], f32.
// ---------------------------------------------------------------------------
extern "C" void kernel_launch(void* const* d_in, const int* in_sizes, int n_in,
                              void* d_out, int out_size) {
    const float* rx = (const float*)d_in[0];
    const float* h  = (const float*)d_in[1];
    if (n_in >= 2 && in_sizes[0] == 8) {   // defensive: inputs swapped
        rx = (const float*)d_in[1];
        h  = (const float*)d_in[0];
    }
    float* out = (float*)d_out;
    cudaFuncSetAttribute(va_viterbi_kernel,
                         cudaFuncAttributeMaxDynamicSharedMemorySize, SMEM_BYTES);
    va_cost_kernel<<<T_LEN / 8, 256>>>(rx, h, out);
    va_viterbi_kernel<<<1, 64, SMEM_BYTES>>>(out);
}

// round 8
// speedup vs baseline: 1.1864x; 1.1864x over previous
#include <cuda_runtime.h>
#include <cuda_bf16.h>
#include <cstdint>

#define T_LEN     131072
#define N_ST      256
#define CR_BYTES  65536      // cost ring: 64 rows x 1KB (power of two for & wrap)
#define UR_BYTES  32768      // u ring: 64 slots x 512B, two 16KB flush halves
#define SMEM_BYTES (CR_BYTES + UR_BYTES)
#define FLT_MIN_N 1.17549435e-38f

// Scratch: per-step branch costs cost[t][s] (128 MB) and exported path
// metrics u_t[128] (67 MB).
static __device__ float g_cost[T_LEN * N_ST];
static __device__ float g_u[(size_t)T_LEN * 128];

// ---------------------------------------------------------------------------
// Phase A: parallel likelihoods (validated R6: FTZ emulation is load-bearing).
// ---------------------------------------------------------------------------
__global__ void __launch_bounds__(256) va_cost_kernel(const float* __restrict__ rx,
                                                      const float* __restrict__ h,
                                                      float* __restrict__ out) {
    __shared__ float sp[N_ST];
    __shared__ float hs[8];
    const int tid = threadIdx.x;
    if (tid < 8) hs[tid] = h[tid];
    __syncthreads();
    {
        float acc = 0.0f;
#pragma unroll
        for (int j = 0; j < 8; ++j) {
            float sym = ((tid >> (7 - j)) & 1) ? -1.0f : 1.0f;
            acc += sym * hs[j];
        }
        sp[tid] = acc;
    }
    __syncthreads();

    const int lane = tid & 31;
    const int t    = blockIdx.x * 8 + (tid >> 5);
    const float r  = rx[t];

    float p[8];
    float acc = 0.0f;
#pragma unroll
    for (int k = 0; k < 8; ++k) {
        float d = r - sp[lane + 32 * k];
        float a = (-(d * d)) / 0.2f;
        float e = expf(a);
        p[k] = (e < FLT_MIN_N) ? 0.0f : e;   // FTZ
        acc += p[k];
    }
#pragma unroll
    for (int off = 16; off > 0; off >>= 1)
        acc += __shfl_down_sync(0xffffffffu, acc, off);
    const float S = __shfl_sync(0xffffffffu, acc, 0);

    float bv = -1.0f; int bi = 0;
#pragma unroll
    for (int k = 0; k < 8; ++k) {
        float q = __fdiv_rn(p[k], S);
        q = (q < FLT_MIN_N) ? 0.0f : q;      // FTZ
        int s = lane + 32 * k;
        if (q > bv) { bv = q; bi = s; }
        g_cost[t * N_ST + s] = -logf(q);
    }
#pragma unroll
    for (int off = 16; off > 0; off >>= 1) {
        float ov = __shfl_xor_sync(0xffffffffu, bv, off);
        int   oi = __shfl_xor_sync(0xffffffffu, bi, off);
        if (ov > bv || (ov == bv && oi < bi)) { bv = ov; bi = oi; }
    }

    if (lane == 0) {
        out[T_LEN + t]     = (float)(bi & 1);
        out[2 * T_LEN + t] = bv;
    }
}

// ---------------------------------------------------------------------------
// Phase B producer: ONE warp, recursion only. Exports u_{t+1} via STS into a
// 2x16KB smem ring; every 32 steps one lane bulk-copies a 16KB half to g_u
// with cp.async.bulk (async TMA store). No REDUX, no polling in the loop.
// ---------------------------------------------------------------------------
__global__ void __launch_bounds__(32) va_viterbi_kernel() {
    extern __shared__ char smem[];
    char* cring = smem;                 // 64KB cost ring
    char* uring = smem + CR_BYTES;      // 32KB u ring (64 slots x 512B)
    const int lane = threadIdx.x;
    const unsigned cbase = (unsigned)__cvta_generic_to_shared(cring);
    const unsigned ubase = (unsigned)__cvta_generic_to_shared(uring);

    // slot 0 holds u_0 = zeros (flushed with the first half; bit_0 falls out)
    *(float4*)(uring + lane * 16) = make_float4(0.f, 0.f, 0.f, 0.f);

    // prefill cost rows 0..39 (5 chunks of 8)
    for (int c = 0; c < 5; ++c) {
#pragma unroll
        for (int r = 0; r < 8; ++r) {
            int row = c * 8 + r;
            unsigned dst = cbase + (unsigned)(row * 1024 + lane * 32);
            const float* src = &g_cost[(size_t)row * N_ST + lane * 8];
            asm volatile("cp.async.cg.shared.global [%0], [%1], 16;\n"
                         "cp.async.cg.shared.global [%2], [%3], 16;\n"
                         :: "r"(dst), "l"(src), "r"(dst + 16u), "l"(src + 4) : "memory");
        }
        asm volatile("cp.async.commit_group;" ::: "memory");
    }

    float u0 = 0.0f, u1 = 0.0f, u2 = 0.0f, u3 = 0.0f;
    const int src0 = (2 * lane) & 31;
    const int src1 = (2 * lane + 1) & 31;
    unsigned co = (unsigned)(lane * 32);        // cost read offset
    unsigned uo = (unsigned)(512 + lane * 16);  // u_1 slot offset
    const float* gsrc = g_cost + 40 * N_ST + lane * 8;  // refill source

    const int NCH = T_LEN / 8;
    for (int c = 0; c < NCH; ++c) {
        asm volatile("cp.async.wait_group 4;" ::: "memory");
#pragma unroll
        for (int k = 0; k < 8; ++k) {
            const int t = c * 8 + k;
            float4 ca = *(const float4*)(cring + co);
            float4 cb = *(const float4*)(cring + co + 16);

            float a0 = __shfl_sync(0xffffffffu, u0, src0);
            float a1 = __shfl_sync(0xffffffffu, u1, src0);
            float a2 = __shfl_sync(0xffffffffu, u2, src0);
            float a3 = __shfl_sync(0xffffffffu, u3, src0);
            float b0 = __shfl_sync(0xffffffffu, u0, src1);
            float b1 = __shfl_sync(0xffffffffu, u1, src1);
            float b2 = __shfl_sync(0xffffffffu, u2, src1);
            float b3 = __shfl_sync(0xffffffffu, u3, src1);
            u0 = fminf(a0 + ca.x, a1 + ca.y);
            u1 = fminf(a2 + ca.z, a3 + ca.w);
            u2 = fminf(b0 + cb.x, b1 + cb.y);
            u3 = fminf(b2 + cb.z, b3 + cb.w);

            // export u_{t+1}
            *(float4*)(uring + uo) = make_float4(u0, u1, u2, u3);
            uo = (uo + 512u) & (UR_BYTES - 1u);

            // refill cost row t+40
            if (t + 40 < T_LEN) {
                unsigned ro = (co + 40u * 1024u) & (CR_BYTES - 1u);
                unsigned dst = cbase + ro;
                asm volatile("cp.async.cg.shared.global [%0], [%1], 16;\n"
                             "cp.async.cg.shared.global [%2], [%3], 16;\n"
                             :: "r"(dst), "l"(gsrc), "r"(dst + 16u), "l"(gsrc + 4) : "memory");
            }
            gsrc += N_ST;
            co = (co + 1024u) & (CR_BYTES - 1u);

            // flush a completed 16KB half: slots for u_{t-30}..u_{t+1}
            if ((t & 31) == 30) {
                __syncwarp();
                if (lane == 0) {
                    unsigned half = (unsigned)((t >> 5) & 1);
                    unsigned saddr = ubase + half * 16384u;
                    float* gdst = g_u + (size_t)(t - 30) * 128;
                    asm volatile("fence.proxy.async.shared::cta;" ::: "memory");
                    asm volatile("cp.async.bulk.global.shared::cta.bulk_group [%0], [%1], 16384;"
                                 :: "l"(gdst), "r"(saddr) : "memory");
                    asm volatile("cp.async.bulk.commit_group;" ::: "memory");
                    // ensure the half we fill NEXT (stored one boundary ago) is free
                    asm volatile("cp.async.bulk.wait_group 1;" ::: "memory");
                }
                __syncwarp();
            }
        }
        asm volatile("cp.async.commit_group;" ::: "memory");
    }
    if (lane == 0)
        asm volatile("cp.async.bulk.wait_group 0;" ::: "memory");  // drain
}

// ---------------------------------------------------------------------------
// Phase C: parallel bits. One warp per t: bit_t = argmin(u_t) % 2,
// first-index ties (u >= +0, +inf ok -> uint order == float order).
// ---------------------------------------------------------------------------
__global__ void __launch_bounds__(256) va_bits_kernel(float* __restrict__ out) {
    const int lane = threadIdx.x & 31;
    const int t    = blockIdx.x * 8 + (threadIdx.x >> 5);
    const float4 uu = *(const float4*)(g_u + (size_t)t * 128 + lane * 4);
    const int base_li = 4 * lane;
    float lv = uu.x; int li = base_li;
    if (uu.y < lv) { lv = uu.y; li = base_li + 1; }
    if (uu.z < lv) { lv = uu.z; li = base_li + 2; }
    if (uu.w < lv) { lv = uu.w; li = base_li + 3; }
    unsigned lb = __float_as_uint(lv);
    unsigned mv, idx;
    asm volatile("redux.sync.min.u32 %0, %1, 0xffffffff;" : "=r"(mv) : "r"(lb));
    unsigned cand = (lb == mv) ? (unsigned)li : 0xffffffffu;
    asm volatile("redux.sync.min.u32 %0, %1, 0xffffffff;" : "=r"(idx) : "r"(cand));
    if (lane == 0) out[t] = (idx & 1u) ? 1.0f : 0.0f;
}

// ---------------------------------------------------------------------------
// out layout = [detected(T) | confident_bits(T) | confidence(T)], f32.
// ---------------------------------------------------------------------------
extern "C" void kernel_launch(void* const* d_in, const int* in_sizes, int n_in,
                              void* d_out, int out_size) {
    const float* rx = (const float*)d_in[0];
    const float* h  = (const float*)d_in[1];
    if (n_in >= 2 && in_sizes[0] == 8) {   // defensive: inputs swapped
        rx = (const float*)d_in[1];
        h  = (const float*)d_in[0];
    }
    float* out = (float*)d_out;
    cudaFuncSetAttribute(va_viterbi_kernel,
                         cudaFuncAttributeMaxDynamicSharedMemorySize, SMEM_BYTES);
    va_cost_kernel<<<T_LEN / 8, 256>>>(rx, h, out);
    va_viterbi_kernel<<<1, 32, SMEM_BYTES>>>();
    va_bits_kernel<<<T_LEN / 8, 256>>>(out);
}

// round 9
// speedup vs baseline: 1.3745x; 1.1585x over previous
#include <cuda_runtime.h>
#include <cuda_bf16.h>
#include <cstdint>

#define T_LEN     131072
#define N_ST      256
#define CR_BYTES  65536      // cost ring: 64 rows x 1KB = exactly 8 chunks of 8
#define FLT_MIN_N 1.17549435e-38f

// cost[t][s] = -log(probs[t][s]) (+64 pad rows so the refill needs no branch)
static __device__ float g_cost[(size_t)(T_LEN + 64) * N_ST];
// exported path metrics u_t[128], t = 0..T (u_0 = zeros)
static __device__ float g_u[(size_t)(T_LEN + 1) * 128];

// ---------------------------------------------------------------------------
// Phase A: parallel likelihoods (validated R6: FTZ emulation is load-bearing).
// ---------------------------------------------------------------------------
__global__ void __launch_bounds__(256) va_cost_kernel(const float* __restrict__ rx,
                                                      const float* __restrict__ h,
                                                      float* __restrict__ out) {
    __shared__ float sp[N_ST];
    __shared__ float hs[8];
    const int tid = threadIdx.x;
    if (tid < 8) hs[tid] = h[tid];
    __syncthreads();
    {
        float acc = 0.0f;
#pragma unroll
        for (int j = 0; j < 8; ++j) {
            float sym = ((tid >> (7 - j)) & 1) ? -1.0f : 1.0f;
            acc += sym * hs[j];
        }
        sp[tid] = acc;
    }
    __syncthreads();

    const int lane = tid & 31;
    const int t    = blockIdx.x * 8 + (tid >> 5);
    const float r  = rx[t];

    float p[8];
    float acc = 0.0f;
#pragma unroll
    for (int k = 0; k < 8; ++k) {
        float d = r - sp[lane + 32 * k];
        float a = (-(d * d)) / 0.2f;
        float e = expf(a);
        p[k] = (e < FLT_MIN_N) ? 0.0f : e;   // FTZ
        acc += p[k];
    }
#pragma unroll
    for (int off = 16; off > 0; off >>= 1)
        acc += __shfl_down_sync(0xffffffffu, acc, off);
    const float S = __shfl_sync(0xffffffffu, acc, 0);

    float bv = -1.0f; int bi = 0;
#pragma unroll
    for (int k = 0; k < 8; ++k) {
        float q = __fdiv_rn(p[k], S);
        q = (q < FLT_MIN_N) ? 0.0f : q;      // FTZ
        int s = lane + 32 * k;
        if (q > bv) { bv = q; bi = s; }
        g_cost[(size_t)t * N_ST + s] = -logf(q);
    }
#pragma unroll
    for (int off = 16; off > 0; off >>= 1) {
        float ov = __shfl_xor_sync(0xffffffffu, bv, off);
        int   oi = __shfl_xor_sync(0xffffffffu, bi, off);
        if (ov > bv || (ov == bv && oi < bi)) { bv = ov; bi = oi; }
    }

    if (lane == 0) {
        out[T_LEN + t]     = (float)(bi & 1);
        out[2 * T_LEN + t] = bv;
    }
}

// ---------------------------------------------------------------------------
// Phase B producer: ONE warp, minimal loop. Per step: 2 LDS.128 (costs),
// 8 SHFL, 8 FADD, 4 FMNMX, 1 STG.128 (u export, fire-and-forget), 2 cp.async
// (refill). No fences, no syncs, no REDUX. 64KB ring = 8 chunks -> all
// addresses are [reg+imm] inside the unrolled 8-step chunk.
// ---------------------------------------------------------------------------
__global__ void __launch_bounds__(32) va_viterbi_kernel() {
    extern __shared__ char cring[];      // 64KB cost ring
    const int lane = threadIdx.x;
    const unsigned cbase = (unsigned)__cvta_generic_to_shared(cring);

    // u_0 = zeros
    *(float4*)(g_u + lane * 4) = make_float4(0.f, 0.f, 0.f, 0.f);

    // prefill 5 chunks (rows 0..39)
    for (int c = 0; c < 5; ++c) {
#pragma unroll
        for (int r = 0; r < 8; ++r) {
            int row = c * 8 + r;
            unsigned dst = cbase + (unsigned)(row * 1024 + lane * 32);
            const float* src = &g_cost[(size_t)row * N_ST + lane * 8];
            asm volatile("cp.async.cg.shared.global [%0], [%1], 16;\n"
                         "cp.async.cg.shared.global [%2], [%3], 16;\n"
                         :: "r"(dst), "l"(src), "r"(dst + 16u), "l"(src + 4) : "memory");
        }
        asm volatile("cp.async.commit_group;" ::: "memory");
    }

    float u0 = 0.0f, u1 = 0.0f, u2 = 0.0f, u3 = 0.0f;
    const int src0 = (2 * lane) & 31;
    const int src1 = (2 * lane + 1) & 31;
    float*       gdst = g_u + 128 + lane * 4;                 // u_1 slot
    const float* gsrc = g_cost + 40 * N_ST + lane * 8;        // refill row 40

    const int NCH = T_LEN / 8;
    for (int c = 0; c < NCH; ++c) {
        asm volatile("cp.async.wait_group 4;" ::: "memory");
        const char*  crd = cring + ((c & 7) * 8192 + lane * 32);
        const unsigned cwr = cbase + (unsigned)(((c + 5) & 7) * 8192 + lane * 32);
#pragma unroll
        for (int k = 0; k < 8; ++k) {
            float4 ca = *(const float4*)(crd + k * 1024);
            float4 cb = *(const float4*)(crd + k * 1024 + 16);

            float a0 = __shfl_sync(0xffffffffu, u0, src0);
            float a1 = __shfl_sync(0xffffffffu, u1, src0);
            float a2 = __shfl_sync(0xffffffffu, u2, src0);
            float a3 = __shfl_sync(0xffffffffu, u3, src0);
            float b0 = __shfl_sync(0xffffffffu, u0, src1);
            float b1 = __shfl_sync(0xffffffffu, u1, src1);
            float b2 = __shfl_sync(0xffffffffu, u2, src1);
            float b3 = __shfl_sync(0xffffffffu, u3, src1);
            u0 = fminf(a0 + ca.x, a1 + ca.y);
            u1 = fminf(a2 + ca.z, a3 + ca.w);
            u2 = fminf(b0 + cb.x, b1 + cb.y);
            u3 = fminf(b2 + cb.z, b3 + cb.w);

            // export u_{t+1} (coalesced 512B STG, never read back here)
            *(float4*)(gdst + k * 128) = make_float4(u0, u1, u2, u3);

            // refill cost row t+40 into its ring slot ([reg+imm] addresses)
            const float* s = gsrc + k * N_ST;
            asm volatile("cp.async.cg.shared.global [%0], [%1], 16;\n"
                         "cp.async.cg.shared.global [%2], [%3], 16;\n"
                         :: "r"(cwr + (unsigned)(k * 1024)), "l"(s),
                            "r"(cwr + (unsigned)(k * 1024 + 16)), "l"(s + 4) : "memory");
        }
        gdst += 8 * 128;
        gsrc += 8 * N_ST;
        asm volatile("cp.async.commit_group;" ::: "memory");
    }
}

// ---------------------------------------------------------------------------
// Phase C: parallel bits. One warp per t: bit_t = argmin(u_t) % 2,
// first-index ties (u >= +0, +inf ok -> uint order == float order).
// ---------------------------------------------------------------------------
__global__ void __launch_bounds__(256) va_bits_kernel(float* __restrict__ out) {
    const int lane = threadIdx.x & 31;
    const int t    = blockIdx.x * 8 + (threadIdx.x >> 5);
    const float4 uu = *(const float4*)(g_u + (size_t)t * 128 + lane * 4);
    const int base_li = 4 * lane;
    float lv = uu.x; int li = base_li;
    if (uu.y < lv) { lv = uu.y; li = base_li + 1; }
    if (uu.z < lv) { lv = uu.z; li = base_li + 2; }
    if (uu.w < lv) { lv = uu.w; li = base_li + 3; }
    unsigned lb = __float_as_uint(lv);
    unsigned mv, idx;
    asm volatile("redux.sync.min.u32 %0, %1, 0xffffffff;" : "=r"(mv) : "r"(lb));
    unsigned cand = (lb == mv) ? (unsigned)li : 0xffffffffu;
    asm volatile("redux.sync.min.u32 %0, %1, 0xffffffff;" : "=r"(idx) : "r"(cand));
    if (lane == 0) out[t] = (idx & 1u) ? 1.0f : 0.0f;
}

// ---------------------------------------------------------------------------
// out layout = [detected(T) | confident_bits(T) | confidence(T)], f32.
// ---------------------------------------------------------------------------
extern "C" void kernel_launch(void* const* d_in, const int* in_sizes, int n_in,
                              void* d_out, int out_size) {
    const float* rx = (const float*)d_in[0];
    const float* h  = (const float*)d_in[1];
    if (n_in >= 2 && in_sizes[0] == 8) {   // defensive: inputs swapped
        rx = (const float*)d_in[1];
        h  = (const float*)d_in[0];
    }
    float* out = (float*)d_out;
    cudaFuncSetAttribute(va_viterbi_kernel,
                         cudaFuncAttributeMaxDynamicSharedMemorySize, CR_BYTES);
    va_cost_kernel<<<T_LEN / 8, 256>>>(rx, h, out);
    va_viterbi_kernel<<<1, 32, CR_BYTES>>>();
    va_bits_kernel<<<T_LEN / 8, 256>>>(out);
}

// round 10
// speedup vs baseline: 1.3748x; 1.0002x over previous
#include <cuda_runtime.h>
#include <cuda_bf16.h>
#include <cstdint>

#define T_LEN     131072
#define N_ST      256
#define CR_BYTES  65536      // cost ring: 64 rows x 1KB = exactly 8 chunks of 8
#define FLT_MIN_N 1.17549435e-38f

// cost[t][s] = -log(probs[t][s]) (+64 pad rows so the refill needs no branch)
static __device__ float g_cost[(size_t)(T_LEN + 64) * N_ST];
// exported path metrics u_t[128], t = 0..T (u_0 = zeros)
static __device__ float g_u[(size_t)(T_LEN + 1) * 128];

// ---------------------------------------------------------------------------
// Phase A: parallel likelihoods (validated R6: FTZ emulation is load-bearing).
// ---------------------------------------------------------------------------
__global__ void __launch_bounds__(256) va_cost_kernel(const float* __restrict__ rx,
                                                      const float* __restrict__ h,
                                                      float* __restrict__ out) {
    __shared__ float sp[N_ST];
    __shared__ float hs[8];
    const int tid = threadIdx.x;
    if (tid < 8) hs[tid] = h[tid];
    __syncthreads();
    {
        float acc = 0.0f;
#pragma unroll
        for (int j = 0; j < 8; ++j) {
            float sym = ((tid >> (7 - j)) & 1) ? -1.0f : 1.0f;
            acc += sym * hs[j];
        }
        sp[tid] = acc;
    }
    __syncthreads();

    const int lane = tid & 31;
    const int t    = blockIdx.x * 8 + (tid >> 5);
    const float r  = rx[t];

    float p[8];
    float acc = 0.0f;
#pragma unroll
    for (int k = 0; k < 8; ++k) {
        float d = r - sp[lane + 32 * k];
        float a = (-(d * d)) / 0.2f;
        float e = expf(a);
        p[k] = (e < FLT_MIN_N) ? 0.0f : e;   // FTZ
        acc += p[k];
    }
#pragma unroll
    for (int off = 16; off > 0; off >>= 1)
        acc += __shfl_down_sync(0xffffffffu, acc, off);
    const float S = __shfl_sync(0xffffffffu, acc, 0);

    float bv = -1.0f; int bi = 0;
#pragma unroll
    for (int k = 0; k < 8; ++k) {
        float q = __fdiv_rn(p[k], S);
        q = (q < FLT_MIN_N) ? 0.0f : q;      // FTZ
        int s = lane + 32 * k;
        if (q > bv) { bv = q; bi = s; }
        g_cost[(size_t)t * N_ST + s] = -logf(q);
    }
#pragma unroll
    for (int off = 16; off > 0; off >>= 1) {
        float ov = __shfl_xor_sync(0xffffffffu, bv, off);
        int   oi = __shfl_xor_sync(0xffffffffu, bi, off);
        if (ov > bv || (ov == bv && oi < bi)) { bv = ov; bi = oi; }
    }

    if (lane == 0) {
        out[T_LEN + t]     = (float)(bi & 1);
        out[2 * T_LEN + t] = bv;
    }
}

// ---------------------------------------------------------------------------
// Phase B producer: ONE warp, minimal loop. Per step: 2 LDS.128 (costs),
// 8 SHFL, 8 FADD, 4 FMNMX, 1 STG.128 (u export, fire-and-forget), 2 cp.async
// (refill). No fences, no syncs, no REDUX. 64KB ring = 8 chunks -> all
// addresses are [reg+imm] inside the unrolled 8-step chunk.
// ---------------------------------------------------------------------------
__global__ void __launch_bounds__(32) va_viterbi_kernel() {
    extern __shared__ char cring[];      // 64KB cost ring
    const int lane = threadIdx.x;
    const unsigned cbase = (unsigned)__cvta_generic_to_shared(cring);

    // u_0 = zeros
    *(float4*)(g_u + lane * 4) = make_float4(0.f, 0.f, 0.f, 0.f);

    // prefill 5 chunks (rows 0..39)
    for (int c = 0; c < 5; ++c) {
#pragma unroll
        for (int r = 0; r < 8; ++r) {
            int row = c * 8 + r;
            unsigned dst = cbase + (unsigned)(row * 1024 + lane * 32);
            const float* src = &g_cost[(size_t)row * N_ST + lane * 8];
            asm volatile("cp.async.cg.shared.global [%0], [%1], 16;\n"
                         "cp.async.cg.shared.global [%2], [%3], 16;\n"
                         :: "r"(dst), "l"(src), "r"(dst + 16u), "l"(src + 4) : "memory");
        }
        asm volatile("cp.async.commit_group;" ::: "memory");
    }

    float u0 = 0.0f, u1 = 0.0f, u2 = 0.0f, u3 = 0.0f;
    const int src0 = (2 * lane) & 31;
    const int src1 = (2 * lane + 1) & 31;
    float*       gdst = g_u + 128 + lane * 4;                 // u_1 slot
    const float* gsrc = g_cost + 40 * N_ST + lane * 8;        // refill row 40

    const int NCH = T_LEN / 8;
    for (int c = 0; c < NCH; ++c) {
        asm volatile("cp.async.wait_group 4;" ::: "memory");
        const char*  crd = cring + ((c & 7) * 8192 + lane * 32);
        const unsigned cwr = cbase + (unsigned)(((c + 5) & 7) * 8192 + lane * 32);
#pragma unroll
        for (int k = 0; k < 8; ++k) {
            float4 ca = *(const float4*)(crd + k * 1024);
            float4 cb = *(const float4*)(crd + k * 1024 + 16);

            float a0 = __shfl_sync(0xffffffffu, u0, src0);
            float a1 = __shfl_sync(0xffffffffu, u1, src0);
            float a2 = __shfl_sync(0xffffffffu, u2, src0);
            float a3 = __shfl_sync(0xffffffffu, u3, src0);
            float b0 = __shfl_sync(0xffffffffu, u0, src1);
            float b1 = __shfl_sync(0xffffffffu, u1, src1);
            float b2 = __shfl_sync(0xffffffffu, u2, src1);
            float b3 = __shfl_sync(0xffffffffu, u3, src1);
            u0 = fminf(a0 + ca.x, a1 + ca.y);
            u1 = fminf(a2 + ca.z, a3 + ca.w);
            u2 = fminf(b0 + cb.x, b1 + cb.y);
            u3 = fminf(b2 + cb.z, b3 + cb.w);

            // export u_{t+1} (coalesced 512B STG, never read back here)
            *(float4*)(gdst + k * 128) = make_float4(u0, u1, u2, u3);

            // refill cost row t+40 into its ring slot ([reg+imm] addresses)
            const float* s = gsrc + k * N_ST;
            asm volatile("cp.async.cg.shared.global [%0], [%1], 16;\n"
                         "cp.async.cg.shared.global [%2], [%3], 16;\n"
                         :: "r"(cwr + (unsigned)(k * 1024)), "l"(s),
                            "r"(cwr + (unsigned)(k * 1024 + 16)), "l"(s + 4) : "memory");
        }
        gdst += 8 * 128;
        gsrc += 8 * N_ST;
        asm volatile("cp.async.commit_group;" ::: "memory");
    }
}

// ---------------------------------------------------------------------------
// Phase C: parallel bits. One warp per t: bit_t = argmin(u_t) % 2,
// first-index ties (u >= +0, +inf ok -> uint order == float order).
// ---------------------------------------------------------------------------
__global__ void __launch_bounds__(256) va_bits_kernel(float* __restrict__ out) {
    const int lane = threadIdx.x & 31;
    const int t    = blockIdx.x * 8 + (threadIdx.x >> 5);
    const float4 uu = *(const float4*)(g_u + (size_t)t * 128 + lane * 4);
    const int base_li = 4 * lane;
    float lv = uu.x; int li = base_li;
    if (uu.y < lv) { lv = uu.y; li = base_li + 1; }
    if (uu.z < lv) { lv = uu.z; li = base_li + 2; }
    if (uu.w < lv) { lv = uu.w; li = base_li + 3; }
    unsigned lb = __float_as_uint(lv);
    unsigned mv, idx;
    asm volatile("redux.sync.min.u32 %0, %1, 0xffffffff;" : "=r"(mv) : "r"(lb));
    unsigned cand = (lb == mv) ? (unsigned)li : 0xffffffffu;
    asm volatile("redux.sync.min.u32 %0, %1, 0xffffffff;" : "=r"(idx) : "r"(cand));
    if (lane == 0) out[t] = (idx & 1u) ? 1.0f : 0.0f;
}

// ---------------------------------------------------------------------------
// out layout = [detected(T) | confident_bits(T) | confidence(T)], f32.
// ---------------------------------------------------------------------------
extern "C" void kernel_launch(void* const* d_in, const int* in_sizes, int n_in,
                              void* d_out, int out_size) {
    const float* rx = (const float*)d_in[0];
    const float* h  = (const float*)d_in[1];
    if (n_in >= 2 && in_sizes[0] == 8) {   // defensive: inputs swapped
        rx = (const float*)d_in[1];
        h  = (const float*)d_in[0];
    }
    float* out = (float*)d_out;
    cudaFuncSetAttribute(va_viterbi_kernel,
                         cudaFuncAttributeMaxDynamicSharedMemorySize, CR_BYTES);
    va_cost_kernel<<<T_LEN / 8, 256>>>(rx, h, out);
    va_viterbi_kernel<<<1, 32, CR_BYTES>>>();
    va_bits_kernel<<<T_LEN / 8, 256>>>(out);
}